// round 4
// baseline (speedup 1.0000x reference)
#include <cuda_runtime.h>
#include <math.h>

#define S_IMG 16384
#define N_TXT 4096
#define DIM   512

// d_out layout (floats): [loss(1) | sel(4096) | zimg(16384*512) | ztxt(4096*512)
//                         | all_pairs(16384*4096) | final_logits(4096*4096)]
static const size_t OFF_SEL  = 1;
static const size_t OFF_ZIMG = 4097;
static const size_t OFF_ZTXT = 8392705;
static const size_t OFF_AP   = 10489857;
static const size_t OFF_FL   = 77598721;

// Aligned scratch (device globals: allocation-free per harness rules)
__device__ float    g_zimg[(size_t)S_IMG * DIM];
__device__ float    g_ztxt[(size_t)N_TXT * DIM];
__device__ float    g_pploss[S_IMG];
__device__ unsigned g_segmin[N_TXT];
__device__ int      g_sel[N_TXT];
__device__ float    g_rowsum[N_TXT];
__device__ int      g_key_is64;

__device__ __forceinline__ float softplus_f(float z) {
    return fmaxf(z, 0.0f) + log1pf(expf(-fabsf(z)));
}

__device__ __forceinline__ int load_key(const int* __restrict__ key, int i) {
    return g_key_is64 ? key[2 * i] : key[i];
}

// ---------------------------------------------------------------------------
// K0: reset atomically-updated scratch (graph replay safe)
// ---------------------------------------------------------------------------
__global__ void init_kernel() {
    int i = blockIdx.x * blockDim.x + threadIdx.x;
    if (i == 0) g_key_is64 = 1;
    if (i < N_TXT) {
        g_segmin[i] = 0x7F800000u;  // +inf bits (all pploss are positive)
        g_sel[i]    = S_IMG;
    }
}

// K0b: key dtype probe. int32 keys: odd words are random keys (some nonzero)
// -> flag 0. int64 keys (<4096): odd words (high halves) all zero -> flag 1.
__global__ void detect_key_kernel(const int* __restrict__ key32) {
    int i = blockIdx.x * blockDim.x + threadIdx.x;  // 0..8191
    if (i < S_IMG / 2 && key32[2 * i + 1] != 0)
        atomicExch(&g_key_is64, 0);
}

// ---------------------------------------------------------------------------
// K1/K2: L2 normalize rows of [rows, 512]
// scratch: REAL device address of g_zimg/g_ztxt (from cudaGetSymbolAddress)
// ---------------------------------------------------------------------------
__global__ void norm_kernel(const float* __restrict__ in,
                            float* __restrict__ scratch,
                            float* __restrict__ out_region) {
    const int row = blockIdx.x;
    const int t   = threadIdx.x;  // 0..127
    float4 x = ((const float4*)(in + (size_t)row * DIM))[t];
    float ss = x.x * x.x + x.y * x.y + x.z * x.z + x.w * x.w;
    #pragma unroll
    for (int o = 16; o > 0; o >>= 1) ss += __shfl_xor_sync(0xFFFFFFFFu, ss, o);
    __shared__ float w[4];
    if ((t & 31) == 0) w[t >> 5] = ss;
    __syncthreads();
    float tot = w[0] + w[1] + w[2] + w[3];
    float sc = 1.0f / (sqrtf(tot) + 1e-12f);
    float4 y = make_float4(x.x * sc, x.y * sc, x.z * sc, x.w * sc);
    ((float4*)(scratch + (size_t)row * DIM))[t] = y;
    float* o = out_region + (size_t)row * DIM + (size_t)t * 4;  // 4B-aligned region
    o[0] = y.x; o[1] = y.y; o[2] = y.z; o[3] = y.w;
}

// ---------------------------------------------------------------------------
// K3: SGEMM  C[m,n] = (sum_k A[m,k]*B[n,k]) * t + bias
// References g_zimg/g_ztxt as device symbols (correct in device code).
// ---------------------------------------------------------------------------
__global__ void __launch_bounds__(256, 2)
gemm_kernel(float* __restrict__ C,
            const float* __restrict__ log_t_p,
            const float* __restrict__ bias_p) {
    __shared__ float As[16][128];
    __shared__ float Bs[16][128];

    const int tid = threadIdx.x;
    const int tx = tid & 15;
    const int ty = tid >> 4;
    const int rowBase = blockIdx.y * 128;
    const int colBase = blockIdx.x * 128;

    const int lr = tid >> 1;
    const int lk = (tid & 1) * 8;

    const float* Aptr = g_zimg + (size_t)(rowBase + lr) * DIM + lk;
    const float* Bptr = g_ztxt + (size_t)(colBase + lr) * DIM + lk;

    float acc[8][8];
    #pragma unroll
    for (int i = 0; i < 8; i++)
        #pragma unroll
        for (int j = 0; j < 8; j++) acc[i][j] = 0.0f;

    for (int k0 = 0; k0 < DIM; k0 += 16) {
        float4 a0 = *(const float4*)(Aptr + k0);
        float4 a1 = *(const float4*)(Aptr + k0 + 4);
        float4 b0 = *(const float4*)(Bptr + k0);
        float4 b1 = *(const float4*)(Bptr + k0 + 4);
        __syncthreads();
        As[lk + 0][lr] = a0.x; As[lk + 1][lr] = a0.y;
        As[lk + 2][lr] = a0.z; As[lk + 3][lr] = a0.w;
        As[lk + 4][lr] = a1.x; As[lk + 5][lr] = a1.y;
        As[lk + 6][lr] = a1.z; As[lk + 7][lr] = a1.w;
        Bs[lk + 0][lr] = b0.x; Bs[lk + 1][lr] = b0.y;
        Bs[lk + 2][lr] = b0.z; Bs[lk + 3][lr] = b0.w;
        Bs[lk + 4][lr] = b1.x; Bs[lk + 5][lr] = b1.y;
        Bs[lk + 6][lr] = b1.z; Bs[lk + 7][lr] = b1.w;
        __syncthreads();
        #pragma unroll
        for (int kk = 0; kk < 16; kk++) {
            float4 a40 = *(const float4*)&As[kk][ty * 8];
            float4 a41 = *(const float4*)&As[kk][ty * 8 + 4];
            float4 b40 = *(const float4*)&Bs[kk][tx * 8];
            float4 b41 = *(const float4*)&Bs[kk][tx * 8 + 4];
            float ra[8] = {a40.x, a40.y, a40.z, a40.w, a41.x, a41.y, a41.z, a41.w};
            float rb[8] = {b40.x, b40.y, b40.z, b40.w, b41.x, b41.y, b41.z, b41.w};
            #pragma unroll
            for (int i = 0; i < 8; i++)
                #pragma unroll
                for (int j = 0; j < 8; j++)
                    acc[i][j] = fmaf(ra[i], rb[j], acc[i][j]);
        }
    }

    const float t = expf(log_t_p[0]);
    const float b = bias_p[0];
    #pragma unroll
    for (int i = 0; i < 8; i++) {
        const int row = rowBase + ty * 8 + i;
        float* Crow = C + (size_t)row * N_TXT + colBase + tx * 8;
        #pragma unroll
        for (int j = 0; j < 8; j++)
            Crow[j] = acc[i][j] * t + b;
    }
}

// ---------------------------------------------------------------------------
// K4: true-positive loss + segment min (bit-ordered atomicMin on positive f32)
// ---------------------------------------------------------------------------
__global__ void tp_kernel(const float* __restrict__ AP, const int* __restrict__ key) {
    int i = blockIdx.x * blockDim.x + threadIdx.x;
    if (i >= S_IMG) return;
    int k = load_key(key, i);
    float lp = AP[(size_t)i * N_TXT + k];
    float p = softplus_f(-lp);
    g_pploss[i] = p;
    atomicMin(&g_segmin[k], __float_as_uint(p));
}

// K5: first-index argmin among exact-min matches
__global__ void argmin_kernel(const int* __restrict__ key) {
    int i = blockIdx.x * blockDim.x + threadIdx.x;
    if (i >= S_IMG) return;
    int k = load_key(key, i);
    if (__float_as_uint(g_pploss[i]) == g_segmin[k])
        atomicMin(&g_sel[k], i);
}

// K6: write selected indices (as float) to d_out
__global__ void sel_kernel(float* __restrict__ out_sel) {
    int n = blockIdx.x * blockDim.x + threadIdx.x;
    if (n >= N_TXT) return;
    int sv = g_sel[n];
    out_sel[n] = (float)(sv < S_IMG ? sv : -1);
}

// ---------------------------------------------------------------------------
// K7: final_logits = gather rows of all_pairs (or bias if invalid);
//     per-row softplus loss sums
// ---------------------------------------------------------------------------
__global__ void __launch_bounds__(256)
final_kernel(const float* __restrict__ AP, float* __restrict__ FL,
             const float* __restrict__ bias_p) {
    const int n = blockIdx.x;
    const int sv = g_sel[n];
    const bool valid = sv < S_IMG;
    const float b = bias_p[0];
    const float* src = AP + (size_t)(valid ? sv : 0) * N_TXT;

    float sum = 0.0f;
    for (int j = threadIdx.x; j < N_TXT; j += 256) {
        float v = valid ? src[j] : b;
        FL[(size_t)n * N_TXT + j] = v;
        float lbl = (j == n) ? 1.0f : -1.0f;
        sum += softplus_f(-(lbl * v));
    }
    __shared__ float sm[256];
    sm[threadIdx.x] = sum;
    __syncthreads();
    #pragma unroll
    for (int o = 128; o > 0; o >>= 1) {
        if (threadIdx.x < o) sm[threadIdx.x] += sm[threadIdx.x + o];
        __syncthreads();
    }
    if (threadIdx.x == 0) g_rowsum[n] = sm[0];
}

// K8: final loss reduction (double)
__global__ void loss_kernel(float* __restrict__ out_loss) {
    __shared__ double sd[256];
    double s = 0.0;
    for (int n = threadIdx.x; n < N_TXT; n += 256) s += (double)g_rowsum[n];
    sd[threadIdx.x] = s;
    __syncthreads();
    #pragma unroll
    for (int o = 128; o > 0; o >>= 1) {
        if (threadIdx.x < o) sd[threadIdx.x] += sd[threadIdx.x + o];
        __syncthreads();
    }
    if (threadIdx.x == 0) out_loss[0] = (float)(sd[0] / (double)N_TXT);
}

// ---------------------------------------------------------------------------
extern "C" void kernel_launch(void* const* d_in, const int* in_sizes, int n_in,
                              void* d_out, int out_size) {
    const float* img   = (const float*)d_in[0];
    const float* txt   = (const float*)d_in[1];
    const int*   key   = (const int*)d_in[2];
    const float* log_t = (const float*)d_in[3];
    const float* bias  = (const float*)d_in[4];
    float* out = (float*)d_out;
    (void)in_sizes; (void)n_in; (void)out_size;

    float* out_sel  = out + OFF_SEL;
    float* out_zimg = out + OFF_ZIMG;
    float* out_ztxt = out + OFF_ZTXT;
    float* out_ap   = out + OFF_AP;
    float* out_fl   = out + OFF_FL;

    // REAL device addresses of the __device__ scratch arrays. Passing the
    // bare symbol from host code passes the host shadow address (the R2/R3
    // bug: g_zimg/g_ztxt stayed zero on device -> AP == 0 -> min-index sel).
    float* zimg_dev = nullptr;
    float* ztxt_dev = nullptr;
    cudaGetSymbolAddress((void**)&zimg_dev, g_zimg);
    cudaGetSymbolAddress((void**)&ztxt_dev, g_ztxt);

    init_kernel<<<(N_TXT + 255) / 256, 256>>>();
    detect_key_kernel<<<(S_IMG / 2 + 255) / 256, 256>>>(key);
    norm_kernel<<<S_IMG, 128>>>(img, zimg_dev, out_zimg);
    norm_kernel<<<N_TXT, 128>>>(txt, ztxt_dev, out_ztxt);

    dim3 grid(N_TXT / 128, S_IMG / 128);
    gemm_kernel<<<grid, 256>>>(out_ap, log_t, bias);

    tp_kernel<<<(S_IMG + 255) / 256, 256>>>(out_ap, key);
    argmin_kernel<<<(S_IMG + 255) / 256, 256>>>(key);
    sel_kernel<<<(N_TXT + 255) / 256, 256>>>(out_sel);

    final_kernel<<<N_TXT, 256>>>(out_ap, out_fl, bias);
    loss_kernel<<<1, 256>>>(out);
}

// round 7
// speedup vs baseline: 2.1466x; 2.1466x over previous
#include <cuda_runtime.h>
#include <cuda_bf16.h>
#include <math.h>
#include <stdint.h>

#define S_IMG 16384
#define N_TXT 4096
#define DIM   512

// d_out layout (floats): [loss(1) | sel(4096) | zimg | ztxt | all_pairs | final_logits]
static const size_t OFF_SEL  = 1;
static const size_t OFF_ZIMG = 4097;
static const size_t OFF_ZTXT = 8392705;
static const size_t OFF_AP   = 10489857;   // ODD -> d_out+OFF_AP only 4B-aligned!
static const size_t OFF_FL   = 77598721;   // ODD as well

// ---------------- device scratch (aligned for vector/cp.async access) -------
__device__ __align__(256) float          g_zimg[(size_t)S_IMG * DIM];
__device__ __align__(256) float          g_ztxt[(size_t)N_TXT * DIM];
__device__ __align__(256) __nv_bfloat16  g_zimg_hi[(size_t)S_IMG * DIM];
__device__ __align__(256) __nv_bfloat16  g_zimg_lo[(size_t)S_IMG * DIM];
__device__ __align__(256) __nv_bfloat16  g_ztxt_hi[(size_t)N_TXT * DIM];
__device__ __align__(256) __nv_bfloat16  g_ztxt_lo[(size_t)N_TXT * DIM];
__device__ float          g_pploss[S_IMG];
__device__ unsigned       g_segmin[N_TXT];
__device__ int            g_sel[N_TXT];
__device__ float          g_rowsum[N_TXT];
__device__ int            g_key_is64;

__device__ __forceinline__ float softplus_f(float z) {
    return fmaxf(z, 0.0f) + log1pf(expf(-fabsf(z)));
}
__device__ __forceinline__ int load_key(const int* __restrict__ key, int i) {
    return g_key_is64 ? key[2 * i] : key[i];
}

// ---------------- portable PTX helpers (compute_103-safe) ----------------
__device__ __forceinline__ uint32_t smem_u32(const void* p) {
    uint32_t a;
    asm("{ .reg .u64 t; cvta.to.shared.u64 t, %1; cvt.u32.u64 %0, t; }" : "=r"(a) : "l"(p));
    return a;
}
__device__ __forceinline__ void cp_async16(uint32_t dst, const void* src) {
    asm volatile("cp.async.cg.shared.global [%0], [%1], 16;" :: "r"(dst), "l"(src));
}
#define CP_COMMIT() asm volatile("cp.async.commit_group;" ::: "memory")
#define CP_WAIT1()  asm volatile("cp.async.wait_group 1;" ::: "memory")

__device__ __forceinline__ void ldmat_x4(uint32_t addr, uint32_t* r) {
    asm volatile("ldmatrix.sync.aligned.m8n8.x4.shared.b16 {%0,%1,%2,%3}, [%4];"
                 : "=r"(r[0]), "=r"(r[1]), "=r"(r[2]), "=r"(r[3]) : "r"(addr));
}
__device__ __forceinline__ void mma16816(float* c, const uint32_t* a, const uint32_t* b) {
    asm volatile(
        "mma.sync.aligned.m16n8k16.row.col.f32.bf16.bf16.f32 "
        "{%0,%1,%2,%3}, {%4,%5,%6,%7}, {%8,%9}, {%0,%1,%2,%3};"
        : "+f"(c[0]), "+f"(c[1]), "+f"(c[2]), "+f"(c[3])
        : "r"(a[0]), "r"(a[1]), "r"(a[2]), "r"(a[3]), "r"(b[0]), "r"(b[1]));
}

// ---------------------------------------------------------------------------
// K0: init + key dtype probe
// ---------------------------------------------------------------------------
__global__ void init_kernel() {
    int i = blockIdx.x * blockDim.x + threadIdx.x;
    if (i == 0) g_key_is64 = 1;
    if (i < N_TXT) {
        g_segmin[i] = 0x7F800000u;
        g_sel[i]    = S_IMG;
    }
}
__global__ void detect_key_kernel(const int* __restrict__ key32) {
    int i = blockIdx.x * blockDim.x + threadIdx.x;
    if (i < S_IMG / 2 && key32[2 * i + 1] != 0)
        atomicExch(&g_key_is64, 0);
}

// ---------------------------------------------------------------------------
// K1/K2: normalize + fp32 scratch + bf16 hi/lo split + d_out copy
// ---------------------------------------------------------------------------
__device__ __forceinline__ void norm_row(const float* __restrict__ in,
                                         float* sc_f32, __nv_bfloat16* sc_hi,
                                         __nv_bfloat16* sc_lo, float* out_region,
                                         int row, int t) {
    float4 x = ((const float4*)(in + (size_t)row * DIM))[t];
    float ss = x.x * x.x + x.y * x.y + x.z * x.z + x.w * x.w;
    #pragma unroll
    for (int o = 16; o > 0; o >>= 1) ss += __shfl_xor_sync(0xFFFFFFFFu, ss, o);
    __shared__ float w[4];
    if ((t & 31) == 0) w[t >> 5] = ss;
    __syncthreads();
    float tot = w[0] + w[1] + w[2] + w[3];
    float sc = 1.0f / (sqrtf(tot) + 1e-12f);
    float y[4] = {x.x * sc, x.y * sc, x.z * sc, x.w * sc};
    ((float4*)(sc_f32 + (size_t)row * DIM))[t] = make_float4(y[0], y[1], y[2], y[3]);
    size_t base = (size_t)row * DIM + (size_t)t * 4;
    #pragma unroll
    for (int e = 0; e < 4; e++) {
        __nv_bfloat16 h = __float2bfloat16_rn(y[e]);
        __nv_bfloat16 l = __float2bfloat16_rn(y[e] - __bfloat162float(h));
        sc_hi[base + e] = h;
        sc_lo[base + e] = l;
        out_region[base + e] = y[e];   // scalar: out_region only 4B-aligned
    }
}
__global__ void norm_img_kernel(const float* __restrict__ in, float* __restrict__ out_region) {
    norm_row(in, g_zimg, g_zimg_hi, g_zimg_lo, out_region, blockIdx.x, threadIdx.x);
}
__global__ void norm_txt_kernel(const float* __restrict__ in, float* __restrict__ out_region) {
    norm_row(in, g_ztxt, g_ztxt_hi, g_ztxt_lo, out_region, blockIdx.x, threadIdx.x);
}

// ---------------------------------------------------------------------------
// K3: HMMA GEMM  C[m,n] = (ahi.bhi + ahi.blo + alo.bhi) * t + bias
// 128x128 CTA tile, 256 threads (2x4 warps, 64x32 per warp), BK=16, 3 stages
// ---------------------------------------------------------------------------
#define BK        16
#define ROW_B     48              // padded row bytes
#define TILE_SB   (128 * ROW_B)   // 6144
#define STAGE_SB  (4 * TILE_SB)   // 24576
#define NSTAGE    3
#define KSTEPS    (DIM / BK)      // 32

__device__ __forceinline__ void load_stage(uint32_t smBase, int stage,
                                           const __nv_bfloat16* Ahi, const __nv_bfloat16* Alo,
                                           const __nv_bfloat16* Bhi, const __nv_bfloat16* Blo,
                                           int k0, int tid) {
    const uint32_t base = smBase + stage * STAGE_SB;
    const int row = tid >> 1;
    const int half = tid & 1;
    const size_t goff = (size_t)row * DIM + k0 + half * 8;   // bf16 elements
    const uint32_t soff = row * ROW_B + half * 16;
    cp_async16(base + 0 * TILE_SB + soff, Ahi + goff);
    cp_async16(base + 1 * TILE_SB + soff, Alo + goff);
    cp_async16(base + 2 * TILE_SB + soff, Bhi + goff);
    cp_async16(base + 3 * TILE_SB + soff, Blo + goff);
}

__global__ void __launch_bounds__(256, 2)
gemm_hmma_kernel(float* __restrict__ C,
                 const float* __restrict__ log_t_p,
                 const float* __restrict__ bias_p) {
    extern __shared__ char smem[];
    const uint32_t smBase = smem_u32(smem);
    const int tid  = threadIdx.x;
    const int wid  = tid >> 5;
    const int lane = tid & 31;
    const int warp_m = wid & 1;
    const int warp_n = wid >> 1;
    const int rowBase = blockIdx.y * 128;
    const int colBase = blockIdx.x * 128;

    const __nv_bfloat16* Ahi = g_zimg_hi + (size_t)rowBase * DIM;
    const __nv_bfloat16* Alo = g_zimg_lo + (size_t)rowBase * DIM;
    const __nv_bfloat16* Bhi = g_ztxt_hi + (size_t)colBase * DIM;
    const __nv_bfloat16* Blo = g_ztxt_lo + (size_t)colBase * DIM;

    float acc[4][4][4];
    #pragma unroll
    for (int i = 0; i < 4; i++)
        #pragma unroll
        for (int j = 0; j < 4; j++)
            #pragma unroll
            for (int f = 0; f < 4; f++) acc[i][j][f] = 0.0f;

    const uint32_t aoff = (uint32_t)((warp_m * 64 + (lane & 15)) * ROW_B + (lane >> 4) * 16);
    const uint32_t boff = (uint32_t)((warp_n * 32 + (lane & 7) + ((lane >> 4) << 3)) * ROW_B +
                                     ((lane >> 3) & 1) * 16);

    load_stage(smBase, 0, Ahi, Alo, Bhi, Blo, 0, tid);  CP_COMMIT();
    load_stage(smBase, 1, Ahi, Alo, Bhi, Blo, BK, tid); CP_COMMIT();

    #pragma unroll 1
    for (int ks = 0; ks < KSTEPS; ks++) {
        CP_WAIT1();
        __syncthreads();
        if (ks + 2 < KSTEPS) {
            load_stage(smBase, (ks + 2) % NSTAGE, Ahi, Alo, Bhi, Blo, (ks + 2) * BK, tid);
            CP_COMMIT();
        }

        const uint32_t st = smBase + (ks % NSTAGE) * STAGE_SB;
        uint32_t afh[4][4], afl[4][4], bf[2][4];

        #pragma unroll
        for (int i = 0; i < 4; i++) {
            ldmat_x4(st + 0 * TILE_SB + aoff + i * 16 * ROW_B, afh[i]);
            ldmat_x4(st + 1 * TILE_SB + aoff + i * 16 * ROW_B, afl[i]);
        }
        #pragma unroll
        for (int j = 0; j < 2; j++) ldmat_x4(st + 2 * TILE_SB + boff + j * 16 * ROW_B, bf[j]);
        #pragma unroll
        for (int i = 0; i < 4; i++)
            #pragma unroll
            for (int j = 0; j < 4; j++)
                mma16816(acc[i][j], afh[i], &bf[j >> 1][(j & 1) * 2]);   // ahi.bhi
        #pragma unroll
        for (int i = 0; i < 4; i++)
            #pragma unroll
            for (int j = 0; j < 4; j++)
                mma16816(acc[i][j], afl[i], &bf[j >> 1][(j & 1) * 2]);   // alo.bhi
        #pragma unroll
        for (int j = 0; j < 2; j++) ldmat_x4(st + 3 * TILE_SB + boff + j * 16 * ROW_B, bf[j]);
        #pragma unroll
        for (int i = 0; i < 4; i++)
            #pragma unroll
            for (int j = 0; j < 4; j++)
                mma16816(acc[i][j], afh[i], &bf[j >> 1][(j & 1) * 2]);   // ahi.blo

        __syncthreads();
    }

    // Epilogue: SCALAR stores only — C is 4B-aligned (OFF_AP is odd).
    const float t = expf(log_t_p[0]);
    const float b = bias_p[0];
    const int mrow0 = rowBase + warp_m * 64 + (lane >> 2);
    const int ncol0 = colBase + warp_n * 32 + 2 * (lane & 3);
    #pragma unroll
    for (int i = 0; i < 4; i++) {
        #pragma unroll
        for (int j = 0; j < 4; j++) {
            size_t r0 = (size_t)(mrow0 + i * 16) * N_TXT + ncol0 + j * 8;
            size_t r1 = r0 + (size_t)8 * N_TXT;
            C[r0 + 0] = acc[i][j][0] * t + b;
            C[r0 + 1] = acc[i][j][1] * t + b;
            C[r1 + 0] = acc[i][j][2] * t + b;
            C[r1 + 1] = acc[i][j][3] * t + b;
        }
    }
}

// ---------------------------------------------------------------------------
// K4: exact fp32 true-positive logits (warp per image) + segment min
// ---------------------------------------------------------------------------
__global__ void tp_kernel(const int* __restrict__ key,
                          const float* __restrict__ log_t_p,
                          const float* __restrict__ bias_p) {
    const int gw = (blockIdx.x * blockDim.x + threadIdx.x) >> 5;
    if (gw >= S_IMG) return;
    const int lane = threadIdx.x & 31;
    const int k = load_key(key, gw);
    const float4* a = (const float4*)(g_zimg + (size_t)gw * DIM);
    const float4* v = (const float4*)(g_ztxt + (size_t)k * DIM);
    float s = 0.0f;
    #pragma unroll
    for (int j = 0; j < 4; j++) {
        float4 x = a[lane + 32 * j], y = v[lane + 32 * j];
        s += x.x * y.x + x.y * y.y + x.z * y.z + x.w * y.w;
    }
    #pragma unroll
    for (int o = 16; o > 0; o >>= 1) s += __shfl_xor_sync(0xFFFFFFFFu, s, o);
    if (lane == 0) {
        float lp = s * expf(log_t_p[0]) + bias_p[0];
        float p = softplus_f(-lp);
        g_pploss[gw] = p;
        atomicMin(&g_segmin[k], __float_as_uint(p));
    }
}

// K5: first-index argmin among exact-min matches
__global__ void argmin_kernel(const int* __restrict__ key) {
    int i = blockIdx.x * blockDim.x + threadIdx.x;
    if (i >= S_IMG) return;
    int k = load_key(key, i);
    if (__float_as_uint(g_pploss[i]) == g_segmin[k])
        atomicMin(&g_sel[k], i);
}

// K6: selected indices (as float) to d_out
__global__ void sel_kernel(float* __restrict__ out_sel) {
    int n = blockIdx.x * blockDim.x + threadIdx.x;
    if (n >= N_TXT) return;
    int sv = g_sel[n];
    out_sel[n] = (float)(sv < S_IMG ? sv : -1);
}

// ---------------------------------------------------------------------------
// K7: final_logits = row gather of all_pairs (bias if invalid) + row loss sums
// ---------------------------------------------------------------------------
__global__ void __launch_bounds__(256)
final_kernel(const float* __restrict__ AP, float* __restrict__ FL,
             const float* __restrict__ bias_p) {
    const int n = blockIdx.x;
    const int sv = g_sel[n];
    const bool valid = sv < S_IMG;
    const float b = bias_p[0];
    const float* src = AP + (size_t)(valid ? sv : 0) * N_TXT;

    float sum = 0.0f;
    for (int j = threadIdx.x; j < N_TXT; j += 256) {
        float v = valid ? src[j] : b;
        FL[(size_t)n * N_TXT + j] = v;
        float lbl = (j == n) ? 1.0f : -1.0f;
        sum += softplus_f(-(lbl * v));
    }
    __shared__ float sm[256];
    sm[threadIdx.x] = sum;
    __syncthreads();
    #pragma unroll
    for (int o = 128; o > 0; o >>= 1) {
        if (threadIdx.x < o) sm[threadIdx.x] += sm[threadIdx.x + o];
        __syncthreads();
    }
    if (threadIdx.x == 0) g_rowsum[n] = sm[0];
}

// K8: final loss reduction (double)
__global__ void loss_kernel(float* __restrict__ out_loss) {
    __shared__ double sd[256];
    double s = 0.0;
    for (int n = threadIdx.x; n < N_TXT; n += 256) s += (double)g_rowsum[n];
    sd[threadIdx.x] = s;
    __syncthreads();
    #pragma unroll
    for (int o = 128; o > 0; o >>= 1) {
        if (threadIdx.x < o) sd[threadIdx.x] += sd[threadIdx.x + o];
        __syncthreads();
    }
    if (threadIdx.x == 0) out_loss[0] = (float)(sd[0] / (double)N_TXT);
}

// ---------------------------------------------------------------------------
extern "C" void kernel_launch(void* const* d_in, const int* in_sizes, int n_in,
                              void* d_out, int out_size) {
    const float* img   = (const float*)d_in[0];
    const float* txt   = (const float*)d_in[1];
    const int*   key   = (const int*)d_in[2];
    const float* log_t = (const float*)d_in[3];
    const float* bias  = (const float*)d_in[4];
    float* out = (float*)d_out;
    (void)in_sizes; (void)n_in; (void)out_size;

    float* out_sel  = out + OFF_SEL;
    float* out_zimg = out + OFF_ZIMG;
    float* out_ztxt = out + OFF_ZTXT;
    float* out_ap   = out + OFF_AP;
    float* out_fl   = out + OFF_FL;

    static int smem_cfg = 0;
    const int smem_bytes = NSTAGE * STAGE_SB;   // 73728
    if (!smem_cfg) {
        cudaFuncSetAttribute(gemm_hmma_kernel,
                             cudaFuncAttributeMaxDynamicSharedMemorySize, smem_bytes);
        smem_cfg = 1;
    }

    init_kernel<<<(N_TXT + 255) / 256, 256>>>();
    detect_key_kernel<<<(S_IMG / 2 + 255) / 256, 256>>>(key);
    norm_img_kernel<<<S_IMG, 128>>>(img, out_zimg);
    norm_txt_kernel<<<N_TXT, 128>>>(txt, out_ztxt);

    dim3 grid(N_TXT / 128, S_IMG / 128);
    gemm_hmma_kernel<<<grid, 256, smem_bytes>>>(out_ap, log_t, bias);

    tp_kernel<<<(S_IMG * 32 + 255) / 256, 256>>>(key, log_t, bias);
    argmin_kernel<<<(S_IMG + 255) / 256, 256>>>(key);
    sel_kernel<<<(N_TXT + 255) / 256, 256>>>(out_sel);

    final_kernel<<<N_TXT, 256>>>(out_ap, out_fl, bias);
    loss_kernel<<<1, 256>>>(out);
}

// round 8
// speedup vs baseline: 2.9934x; 1.3945x over previous
#include <cuda_runtime.h>
#include <cuda_fp16.h>
#include <math.h>
#include <stdint.h>

#define S_IMG 16384
#define N_TXT 4096
#define DIM   512

// d_out layout (floats): [loss(1) | sel(4096) | zimg | ztxt | all_pairs | final_logits]
static const size_t OFF_SEL  = 1;
static const size_t OFF_ZIMG = 4097;
static const size_t OFF_ZTXT = 8392705;
static const size_t OFF_AP   = 10489857;   // ODD -> d_out+OFF_AP only 4B-aligned!
static const size_t OFF_FL   = 77598721;   // ODD as well

// ---------------- device scratch (aligned for vector/cp.async access) -------
__device__ __align__(256) float   g_zimg[(size_t)S_IMG * DIM];
__device__ __align__(256) float   g_ztxt[(size_t)N_TXT * DIM];
__device__ __align__(256) __half  g_zimg_h[(size_t)S_IMG * DIM];
__device__ __align__(256) __half  g_zimg_l[(size_t)S_IMG * DIM];
__device__ __align__(256) __half  g_ztxt_h[(size_t)N_TXT * DIM];
__device__ float          g_pploss[S_IMG];
__device__ unsigned       g_segmin[N_TXT];
__device__ int            g_sel[N_TXT];
__device__ float          g_rowsum[N_TXT];
__device__ int            g_key_is64;

__device__ __forceinline__ float softplus_f(float z) {
    return fmaxf(z, 0.0f) + log1pf(expf(-fabsf(z)));
}
__device__ __forceinline__ int load_key(const int* __restrict__ key, int i) {
    return g_key_is64 ? key[2 * i] : key[i];
}

// ---------------- portable PTX helpers (compute_103-safe) ----------------
__device__ __forceinline__ uint32_t smem_u32(const void* p) {
    uint32_t a;
    asm("{ .reg .u64 t; cvta.to.shared.u64 t, %1; cvt.u32.u64 %0, t; }" : "=r"(a) : "l"(p));
    return a;
}
__device__ __forceinline__ void cp_async16(uint32_t dst, const void* src) {
    asm volatile("cp.async.cg.shared.global [%0], [%1], 16;" :: "r"(dst), "l"(src));
}
#define CP_COMMIT() asm volatile("cp.async.commit_group;" ::: "memory")
#define CP_WAIT0()  asm volatile("cp.async.wait_group 0;" ::: "memory")
#define CP_WAIT1()  asm volatile("cp.async.wait_group 1;" ::: "memory")

__device__ __forceinline__ void ldmat_x4(uint32_t addr, uint32_t* r) {
    asm volatile("ldmatrix.sync.aligned.m8n8.x4.shared.b16 {%0,%1,%2,%3}, [%4];"
                 : "=r"(r[0]), "=r"(r[1]), "=r"(r[2]), "=r"(r[3]) : "r"(addr));
}
__device__ __forceinline__ void mma16816(float* c, const uint32_t* a, const uint32_t* b) {
    asm volatile(
        "mma.sync.aligned.m16n8k16.row.col.f32.f16.f16.f32 "
        "{%0,%1,%2,%3}, {%4,%5,%6,%7}, {%8,%9}, {%0,%1,%2,%3};"
        : "+f"(c[0]), "+f"(c[1]), "+f"(c[2]), "+f"(c[3])
        : "r"(a[0]), "r"(a[1]), "r"(a[2]), "r"(a[3]), "r"(b[0]), "r"(b[1]));
}

// ---------------------------------------------------------------------------
// K0: init + key dtype probe
// ---------------------------------------------------------------------------
__global__ void init_kernel() {
    int i = blockIdx.x * blockDim.x + threadIdx.x;
    if (i == 0) g_key_is64 = 1;
    if (i < N_TXT) {
        g_segmin[i] = 0x7F800000u;
        g_sel[i]    = S_IMG;
    }
}
__global__ void detect_key_kernel(const int* __restrict__ key32) {
    int i = blockIdx.x * blockDim.x + threadIdx.x;
    if (i < S_IMG / 2 && key32[2 * i + 1] != 0)
        atomicExch(&g_key_is64, 0);
}

// ---------------------------------------------------------------------------
// K1: normalize img -> fp32 scratch + fp16 hi/lo + d_out copy
// K2: normalize txt -> fp32 scratch + fp16 (hi only) + d_out copy
// ---------------------------------------------------------------------------
__global__ void norm_img_kernel(const float* __restrict__ in, float* __restrict__ out_region) {
    const int row = blockIdx.x, t = threadIdx.x;
    float4 x = ((const float4*)(in + (size_t)row * DIM))[t];
    float ss = x.x * x.x + x.y * x.y + x.z * x.z + x.w * x.w;
    #pragma unroll
    for (int o = 16; o > 0; o >>= 1) ss += __shfl_xor_sync(0xFFFFFFFFu, ss, o);
    __shared__ float w[4];
    if ((t & 31) == 0) w[t >> 5] = ss;
    __syncthreads();
    float sc = 1.0f / (sqrtf(w[0] + w[1] + w[2] + w[3]) + 1e-12f);
    float y[4] = {x.x * sc, x.y * sc, x.z * sc, x.w * sc};
    ((float4*)(g_zimg + (size_t)row * DIM))[t] = make_float4(y[0], y[1], y[2], y[3]);
    size_t base = (size_t)row * DIM + (size_t)t * 4;
    #pragma unroll
    for (int e = 0; e < 4; e++) {
        __half h = __float2half_rn(y[e]);
        g_zimg_h[base + e] = h;
        g_zimg_l[base + e] = __float2half_rn(y[e] - __half2float(h));
        out_region[base + e] = y[e];   // scalar: region only 4B-aligned
    }
}
__global__ void norm_txt_kernel(const float* __restrict__ in, float* __restrict__ out_region) {
    const int row = blockIdx.x, t = threadIdx.x;
    float4 x = ((const float4*)(in + (size_t)row * DIM))[t];
    float ss = x.x * x.x + x.y * x.y + x.z * x.z + x.w * x.w;
    #pragma unroll
    for (int o = 16; o > 0; o >>= 1) ss += __shfl_xor_sync(0xFFFFFFFFu, ss, o);
    __shared__ float w[4];
    if ((t & 31) == 0) w[t >> 5] = ss;
    __syncthreads();
    float sc = 1.0f / (sqrtf(w[0] + w[1] + w[2] + w[3]) + 1e-12f);
    float y[4] = {x.x * sc, x.y * sc, x.z * sc, x.w * sc};
    ((float4*)(g_ztxt + (size_t)row * DIM))[t] = make_float4(y[0], y[1], y[2], y[3]);
    size_t base = (size_t)row * DIM + (size_t)t * 4;
    #pragma unroll
    for (int e = 0; e < 4; e++) {
        g_ztxt_h[base + e] = __float2half_rn(y[e]);
        out_region[base + e] = y[e];
    }
}

// ---------------------------------------------------------------------------
// K3: HMMA GEMM  C[m,n] = ((ah+al).bh) * t + bias   (2 fp16 passes)
// 128x128 CTA tile, 256 threads (2x4 warps, 64x32 per warp), BK=16, 3 stages
// smem/stage: 3 tiles x 128 rows x 48B = 18432 B
// ---------------------------------------------------------------------------
#define BK        16
#define ROW_B     48
#define TILE_SB   (128 * ROW_B)   // 6144
#define STAGE_SB  (3 * TILE_SB)   // 18432
#define NSTAGE    3
#define KSTEPS    (DIM / BK)      // 32

__device__ __forceinline__ void load_stage(uint32_t smBase, int stage,
                                           const __half* Ah, const __half* Al,
                                           const __half* Bh, int k0, int tid) {
    const uint32_t base = smBase + stage * STAGE_SB;
    const int row = tid >> 1;
    const int half = tid & 1;
    const size_t goff = (size_t)row * DIM + k0 + half * 8;   // fp16 elements
    const uint32_t soff = row * ROW_B + half * 16;
    cp_async16(base + 0 * TILE_SB + soff, Ah + goff);
    cp_async16(base + 1 * TILE_SB + soff, Al + goff);
    cp_async16(base + 2 * TILE_SB + soff, Bh + goff);
}

__global__ void __launch_bounds__(256, 2)
gemm_hmma_kernel(float* __restrict__ C,
                 const float* __restrict__ log_t_p,
                 const float* __restrict__ bias_p) {
    extern __shared__ char smem[];
    const uint32_t smBase = smem_u32(smem);
    const int tid  = threadIdx.x;
    const int wid  = tid >> 5;
    const int lane = tid & 31;
    const int warp_m = wid & 1;
    const int warp_n = wid >> 1;
    const int rowBase = blockIdx.y * 128;
    const int colBase = blockIdx.x * 128;

    const __half* Ah = g_zimg_h + (size_t)rowBase * DIM;
    const __half* Al = g_zimg_l + (size_t)rowBase * DIM;
    const __half* Bh = g_ztxt_h + (size_t)colBase * DIM;

    float acc[4][4][4];
    #pragma unroll
    for (int i = 0; i < 4; i++)
        #pragma unroll
        for (int j = 0; j < 4; j++)
            #pragma unroll
            for (int f = 0; f < 4; f++) acc[i][j][f] = 0.0f;

    const uint32_t aoff = (uint32_t)((warp_m * 64 + (lane & 15)) * ROW_B + (lane >> 4) * 16);
    const uint32_t boff = (uint32_t)((warp_n * 32 + (lane & 7) + ((lane >> 4) << 3)) * ROW_B +
                                     ((lane >> 3) & 1) * 16);

    load_stage(smBase, 0, Ah, Al, Bh, 0, tid);  CP_COMMIT();
    load_stage(smBase, 1, Ah, Al, Bh, BK, tid); CP_COMMIT();

    #pragma unroll 1
    for (int ks = 0; ks < KSTEPS; ks++) {
        if (ks == KSTEPS - 1) { CP_WAIT0(); } else { CP_WAIT1(); }
        __syncthreads();
        if (ks + 2 < KSTEPS) {
            load_stage(smBase, (ks + 2) % NSTAGE, Ah, Al, Bh, (ks + 2) * BK, tid);
            CP_COMMIT();
        }

        const uint32_t st = smBase + (ks % NSTAGE) * STAGE_SB;
        uint32_t afh[4][4], afl[4][4], bfr[2][4];

        #pragma unroll
        for (int i = 0; i < 4; i++) {
            ldmat_x4(st + 0 * TILE_SB + aoff + i * 16 * ROW_B, afh[i]);
            ldmat_x4(st + 1 * TILE_SB + aoff + i * 16 * ROW_B, afl[i]);
        }
        #pragma unroll
        for (int j = 0; j < 2; j++)
            ldmat_x4(st + 2 * TILE_SB + boff + j * 16 * ROW_B, bfr[j]);

        #pragma unroll
        for (int i = 0; i < 4; i++)
            #pragma unroll
            for (int j = 0; j < 4; j++)
                mma16816(acc[i][j], afh[i], &bfr[j >> 1][(j & 1) * 2]);   // ah.bh
        #pragma unroll
        for (int i = 0; i < 4; i++)
            #pragma unroll
            for (int j = 0; j < 4; j++)
                mma16816(acc[i][j], afl[i], &bfr[j >> 1][(j & 1) * 2]);   // al.bh
    }

    // Epilogue: SCALAR stores only — C is 4B-aligned (OFF_AP is odd).
    const float t = expf(log_t_p[0]);
    const float b = bias_p[0];
    const int mrow0 = rowBase + warp_m * 64 + (lane >> 2);
    const int ncol0 = colBase + warp_n * 32 + 2 * (lane & 3);
    #pragma unroll
    for (int i = 0; i < 4; i++) {
        #pragma unroll
        for (int j = 0; j < 4; j++) {
            size_t r0 = (size_t)(mrow0 + i * 16) * N_TXT + ncol0 + j * 8;
            size_t r1 = r0 + (size_t)8 * N_TXT;
            C[r0 + 0] = acc[i][j][0] * t + b;
            C[r0 + 1] = acc[i][j][1] * t + b;
            C[r1 + 0] = acc[i][j][2] * t + b;
            C[r1 + 1] = acc[i][j][3] * t + b;
        }
    }
}

// ---------------------------------------------------------------------------
// K4: exact fp32 true-positive logits (warp per image) + segment min
// ---------------------------------------------------------------------------
__global__ void tp_kernel(const int* __restrict__ key,
                          const float* __restrict__ log_t_p,
                          const float* __restrict__ bias_p) {
    const int gw = (blockIdx.x * blockDim.x + threadIdx.x) >> 5;
    if (gw >= S_IMG) return;
    const int lane = threadIdx.x & 31;
    const int k = load_key(key, gw);
    const float4* a = (const float4*)(g_zimg + (size_t)gw * DIM);
    const float4* v = (const float4*)(g_ztxt + (size_t)k * DIM);
    float s = 0.0f;
    #pragma unroll
    for (int j = 0; j < 4; j++) {
        float4 x = a[lane + 32 * j], y = v[lane + 32 * j];
        s += x.x * y.x + x.y * y.y + x.z * y.z + x.w * y.w;
    }
    #pragma unroll
    for (int o = 16; o > 0; o >>= 1) s += __shfl_xor_sync(0xFFFFFFFFu, s, o);
    if (lane == 0) {
        float lp = s * expf(log_t_p[0]) + bias_p[0];
        float p = softplus_f(-lp);
        g_pploss[gw] = p;
        atomicMin(&g_segmin[k], __float_as_uint(p));
    }
}

// K5: first-index argmin among exact-min matches
__global__ void argmin_kernel(const int* __restrict__ key) {
    int i = blockIdx.x * blockDim.x + threadIdx.x;
    if (i >= S_IMG) return;
    int k = load_key(key, i);
    if (__float_as_uint(g_pploss[i]) == g_segmin[k])
        atomicMin(&g_sel[k], i);
}

// K6: selected indices (as float) to d_out
__global__ void sel_kernel(float* __restrict__ out_sel) {
    int n = blockIdx.x * blockDim.x + threadIdx.x;
    if (n >= N_TXT) return;
    int sv = g_sel[n];
    out_sel[n] = (float)(sv < S_IMG ? sv : -1);
}

// ---------------------------------------------------------------------------
// K7: final_logits = row gather of all_pairs (bias if invalid) + row loss sums
// ---------------------------------------------------------------------------
__global__ void __launch_bounds__(256)
final_kernel(const float* __restrict__ AP, float* __restrict__ FL,
             const float* __restrict__ bias_p) {
    const int n = blockIdx.x;
    const int sv = g_sel[n];
    const bool valid = sv < S_IMG;
    const float b = bias_p[0];
    const float* src = AP + (size_t)(valid ? sv : 0) * N_TXT;

    float sum = 0.0f;
    for (int j = threadIdx.x; j < N_TXT; j += 256) {
        float v = valid ? src[j] : b;
        FL[(size_t)n * N_TXT + j] = v;
        float lbl = (j == n) ? 1.0f : -1.0f;
        sum += softplus_f(-(lbl * v));
    }
    __shared__ float sm[256];
    sm[threadIdx.x] = sum;
    __syncthreads();
    #pragma unroll
    for (int o = 128; o > 0; o >>= 1) {
        if (threadIdx.x < o) sm[threadIdx.x] += sm[threadIdx.x + o];
        __syncthreads();
    }
    if (threadIdx.x == 0) g_rowsum[n] = sm[0];
}

// K8: final loss reduction (double)
__global__ void loss_kernel(float* __restrict__ out_loss) {
    __shared__ double sd[256];
    double s = 0.0;
    for (int n = threadIdx.x; n < N_TXT; n += 256) s += (double)g_rowsum[n];
    sd[threadIdx.x] = s;
    __syncthreads();
    #pragma unroll
    for (int o = 128; o > 0; o >>= 1) {
        if (threadIdx.x < o) sd[threadIdx.x] += sd[threadIdx.x + o];
        __syncthreads();
    }
    if (threadIdx.x == 0) out_loss[0] = (float)(sd[0] / (double)N_TXT);
}

// ---------------------------------------------------------------------------
extern "C" void kernel_launch(void* const* d_in, const int* in_sizes, int n_in,
                              void* d_out, int out_size) {
    const float* img   = (const float*)d_in[0];
    const float* txt   = (const float*)d_in[1];
    const int*   key   = (const int*)d_in[2];
    const float* log_t = (const float*)d_in[3];
    const float* bias  = (const float*)d_in[4];
    float* out = (float*)d_out;
    (void)in_sizes; (void)n_in; (void)out_size;

    float* out_sel  = out + OFF_SEL;
    float* out_zimg = out + OFF_ZIMG;
    float* out_ztxt = out + OFF_ZTXT;
    float* out_ap   = out + OFF_AP;
    float* out_fl   = out + OFF_FL;

    static int smem_cfg = 0;
    const int smem_bytes = NSTAGE * STAGE_SB;   // 55296
    if (!smem_cfg) {
        cudaFuncSetAttribute(gemm_hmma_kernel,
                             cudaFuncAttributeMaxDynamicSharedMemorySize, smem_bytes);
        smem_cfg = 1;
    }

    init_kernel<<<(N_TXT + 255) / 256, 256>>>();
    detect_key_kernel<<<(S_IMG / 2 + 255) / 256, 256>>>(key);
    norm_img_kernel<<<S_IMG, 128>>>(img, out_zimg);
    norm_txt_kernel<<<N_TXT, 128>>>(txt, out_ztxt);

    dim3 grid(N_TXT / 128, S_IMG / 128);
    gemm_hmma_kernel<<<grid, 256, smem_bytes>>>(out_ap, log_t, bias);

    tp_kernel<<<(S_IMG * 32 + 255) / 256, 256>>>(key, log_t, bias);
    argmin_kernel<<<(S_IMG + 255) / 256, 256>>>(key);
    sel_kernel<<<(N_TXT + 255) / 256, 256>>>(out_sel);

    final_kernel<<<N_TXT, 256>>>(out_ap, out_fl, bias);
    loss_kernel<<<1, 256>>>(out);
}

// round 9
// speedup vs baseline: 4.0649x; 1.3580x over previous
#include <cuda_runtime.h>
#include <cuda_fp16.h>
#include <math.h>
#include <stdint.h>

#define S_IMG 16384
#define N_TXT 4096
#define DIM   512

// d_out layout (floats): [loss(1) | sel(4096) | zimg | ztxt | all_pairs | final_logits]
static const size_t OFF_SEL  = 1;
static const size_t OFF_ZIMG = 4097;
static const size_t OFF_ZTXT = 8392705;
static const size_t OFF_AP   = 10489857;   // ODD -> d_out+OFF_AP only 4B-aligned!
static const size_t OFF_FL   = 77598721;   // ODD as well

// ---------------- device scratch (aligned for vector/cp.async access) -------
__device__ __align__(256) float   g_zimg[(size_t)S_IMG * DIM];
__device__ __align__(256) float   g_ztxt[(size_t)N_TXT * DIM];
__device__ __align__(256) __half  g_zimg_h[(size_t)S_IMG * DIM];
__device__ __align__(256) __half  g_ztxt_h[(size_t)N_TXT * DIM];
__device__ float          g_pploss[S_IMG];
__device__ unsigned       g_segmin[N_TXT];
__device__ int            g_sel[N_TXT];
__device__ float          g_rowsum[N_TXT];
__device__ int            g_key_is64;

__device__ __forceinline__ float softplus_f(float z) {
    return fmaxf(z, 0.0f) + log1pf(expf(-fabsf(z)));
}
__device__ __forceinline__ int load_key(const int* __restrict__ key, int i) {
    return g_key_is64 ? key[2 * i] : key[i];
}

// ---------------- portable PTX helpers (compute_103-safe) ----------------
__device__ __forceinline__ uint32_t smem_u32(const void* p) {
    uint32_t a;
    asm("{ .reg .u64 t; cvta.to.shared.u64 t, %1; cvt.u32.u64 %0, t; }" : "=r"(a) : "l"(p));
    return a;
}
__device__ __forceinline__ void cp_async16(uint32_t dst, const void* src) {
    asm volatile("cp.async.cg.shared.global [%0], [%1], 16;" :: "r"(dst), "l"(src));
}
#define CP_COMMIT() asm volatile("cp.async.commit_group;" ::: "memory")
#define CP_WAIT0()  asm volatile("cp.async.wait_group 0;" ::: "memory")
#define CP_WAIT1()  asm volatile("cp.async.wait_group 1;" ::: "memory")

__device__ __forceinline__ void ldmat_x4(uint32_t addr, uint32_t* r) {
    asm volatile("ldmatrix.sync.aligned.m8n8.x4.shared.b16 {%0,%1,%2,%3}, [%4];"
                 : "=r"(r[0]), "=r"(r[1]), "=r"(r[2]), "=r"(r[3]) : "r"(addr));
}
__device__ __forceinline__ void mma16816(float* c, const uint32_t* a, const uint32_t* b) {
    asm volatile(
        "mma.sync.aligned.m16n8k16.row.col.f32.f16.f16.f32 "
        "{%0,%1,%2,%3}, {%4,%5,%6,%7}, {%8,%9}, {%0,%1,%2,%3};"
        : "+f"(c[0]), "+f"(c[1]), "+f"(c[2]), "+f"(c[3])
        : "r"(a[0]), "r"(a[1]), "r"(a[2]), "r"(a[3]), "r"(b[0]), "r"(b[1]));
}

// ---------------------------------------------------------------------------
// K0: init + key dtype probe
// ---------------------------------------------------------------------------
__global__ void init_kernel() {
    int i = blockIdx.x * blockDim.x + threadIdx.x;
    if (i == 0) g_key_is64 = 1;
    if (i < N_TXT) {
        g_segmin[i] = 0x7F800000u;
        g_sel[i]    = S_IMG;
    }
}
__global__ void detect_key_kernel(const int* __restrict__ key32) {
    int i = blockIdx.x * blockDim.x + threadIdx.x;
    if (i < S_IMG / 2 && key32[2 * i + 1] != 0)
        atomicExch(&g_key_is64, 0);
}

// ---------------------------------------------------------------------------
// K1/K2: normalize -> fp32 scratch + fp16 + d_out copy
// ---------------------------------------------------------------------------
__global__ void norm_img_kernel(const float* __restrict__ in, float* __restrict__ out_region) {
    const int row = blockIdx.x, t = threadIdx.x;
    float4 x = ((const float4*)(in + (size_t)row * DIM))[t];
    float ss = x.x * x.x + x.y * x.y + x.z * x.z + x.w * x.w;
    #pragma unroll
    for (int o = 16; o > 0; o >>= 1) ss += __shfl_xor_sync(0xFFFFFFFFu, ss, o);
    __shared__ float w[4];
    if ((t & 31) == 0) w[t >> 5] = ss;
    __syncthreads();
    float sc = 1.0f / (sqrtf(w[0] + w[1] + w[2] + w[3]) + 1e-12f);
    float y[4] = {x.x * sc, x.y * sc, x.z * sc, x.w * sc};
    ((float4*)(g_zimg + (size_t)row * DIM))[t] = make_float4(y[0], y[1], y[2], y[3]);
    size_t base = (size_t)row * DIM + (size_t)t * 4;
    #pragma unroll
    for (int e = 0; e < 4; e++) {
        g_zimg_h[base + e] = __float2half_rn(y[e]);
        out_region[base + e] = y[e];   // scalar: region only 4B-aligned
    }
}
__global__ void norm_txt_kernel(const float* __restrict__ in, float* __restrict__ out_region) {
    const int row = blockIdx.x, t = threadIdx.x;
    float4 x = ((const float4*)(in + (size_t)row * DIM))[t];
    float ss = x.x * x.x + x.y * x.y + x.z * x.z + x.w * x.w;
    #pragma unroll
    for (int o = 16; o > 0; o >>= 1) ss += __shfl_xor_sync(0xFFFFFFFFu, ss, o);
    __shared__ float w[4];
    if ((t & 31) == 0) w[t >> 5] = ss;
    __syncthreads();
    float sc = 1.0f / (sqrtf(w[0] + w[1] + w[2] + w[3]) + 1e-12f);
    float y[4] = {x.x * sc, x.y * sc, x.z * sc, x.w * sc};
    ((float4*)(g_ztxt + (size_t)row * DIM))[t] = make_float4(y[0], y[1], y[2], y[3]);
    size_t base = (size_t)row * DIM + (size_t)t * 4;
    #pragma unroll
    for (int e = 0; e < 4; e++) {
        g_ztxt_h[base + e] = __float2half_rn(y[e]);
        out_region[base + e] = y[e];
    }
}

// ---------------------------------------------------------------------------
// K3: HMMA GEMM  C[m,n] = (ah.bh) * t + bias   (single fp16 pass)
// 128x128 CTA tile, 256 threads (2x4 warps, 64x32 per warp), BK=16, 3 stages
// smem/stage: 2 tiles x 128 rows x 48B = 12288 B
// ---------------------------------------------------------------------------
#define BK        16
#define ROW_B     48
#define TILE_SB   (128 * ROW_B)   // 6144
#define STAGE_SB  (2 * TILE_SB)   // 12288
#define NSTAGE    3
#define KSTEPS    (DIM / BK)      // 32

__device__ __forceinline__ void load_stage(uint32_t smBase, int stage,
                                           const __half* Ah, const __half* Bh,
                                           int k0, int tid) {
    const uint32_t base = smBase + stage * STAGE_SB;
    const int row = tid >> 1;
    const int half = tid & 1;
    const size_t goff = (size_t)row * DIM + k0 + half * 8;   // fp16 elements
    const uint32_t soff = row * ROW_B + half * 16;
    cp_async16(base + 0 * TILE_SB + soff, Ah + goff);
    cp_async16(base + 1 * TILE_SB + soff, Bh + goff);
}

__global__ void __launch_bounds__(256, 2)
gemm_hmma_kernel(float* __restrict__ C,
                 const float* __restrict__ log_t_p,
                 const float* __restrict__ bias_p) {
    extern __shared__ char smem[];
    const uint32_t smBase = smem_u32(smem);
    const int tid  = threadIdx.x;
    const int wid  = tid >> 5;
    const int lane = tid & 31;
    const int warp_m = wid & 1;
    const int warp_n = wid >> 1;
    const int rowBase = blockIdx.y * 128;
    const int colBase = blockIdx.x * 128;

    const __half* Ah = g_zimg_h + (size_t)rowBase * DIM;
    const __half* Bh = g_ztxt_h + (size_t)colBase * DIM;

    float acc[4][4][4];
    #pragma unroll
    for (int i = 0; i < 4; i++)
        #pragma unroll
        for (int j = 0; j < 4; j++)
            #pragma unroll
            for (int f = 0; f < 4; f++) acc[i][j][f] = 0.0f;

    const uint32_t aoff = (uint32_t)((warp_m * 64 + (lane & 15)) * ROW_B + (lane >> 4) * 16);
    const uint32_t boff = (uint32_t)((warp_n * 32 + (lane & 7) + ((lane >> 4) << 3)) * ROW_B +
                                     ((lane >> 3) & 1) * 16);

    load_stage(smBase, 0, Ah, Bh, 0, tid);  CP_COMMIT();
    load_stage(smBase, 1, Ah, Bh, BK, tid); CP_COMMIT();

    #pragma unroll 1
    for (int ks = 0; ks < KSTEPS; ks++) {
        if (ks == KSTEPS - 1) { CP_WAIT0(); } else { CP_WAIT1(); }
        __syncthreads();
        if (ks + 2 < KSTEPS) {
            load_stage(smBase, (ks + 2) % NSTAGE, Ah, Bh, (ks + 2) * BK, tid);
            CP_COMMIT();
        }

        const uint32_t st = smBase + (ks % NSTAGE) * STAGE_SB;
        uint32_t afh[4][4], bfr[2][4];

        #pragma unroll
        for (int i = 0; i < 4; i++)
            ldmat_x4(st + 0 * TILE_SB + aoff + i * 16 * ROW_B, afh[i]);
        #pragma unroll
        for (int j = 0; j < 2; j++)
            ldmat_x4(st + 1 * TILE_SB + boff + j * 16 * ROW_B, bfr[j]);

        #pragma unroll
        for (int i = 0; i < 4; i++)
            #pragma unroll
            for (int j = 0; j < 4; j++)
                mma16816(acc[i][j], afh[i], &bfr[j >> 1][(j & 1) * 2]);   // ah.bh
    }

    // Epilogue: SCALAR stores only — C is 4B-aligned (OFF_AP is odd).
    const float t = expf(log_t_p[0]);
    const float b = bias_p[0];
    const int mrow0 = rowBase + warp_m * 64 + (lane >> 2);
    const int ncol0 = colBase + warp_n * 32 + 2 * (lane & 3);
    #pragma unroll
    for (int i = 0; i < 4; i++) {
        #pragma unroll
        for (int j = 0; j < 4; j++) {
            size_t r0 = (size_t)(mrow0 + i * 16) * N_TXT + ncol0 + j * 8;
            size_t r1 = r0 + (size_t)8 * N_TXT;
            C[r0 + 0] = acc[i][j][0] * t + b;
            C[r0 + 1] = acc[i][j][1] * t + b;
            C[r1 + 0] = acc[i][j][2] * t + b;
            C[r1 + 1] = acc[i][j][3] * t + b;
        }
    }
}

// ---------------------------------------------------------------------------
// K4: exact fp32 true-positive logits (warp per image) + segment min
// ---------------------------------------------------------------------------
__global__ void tp_kernel(const int* __restrict__ key,
                          const float* __restrict__ log_t_p,
                          const float* __restrict__ bias_p) {
    const int gw = (blockIdx.x * blockDim.x + threadIdx.x) >> 5;
    if (gw >= S_IMG) return;
    const int lane = threadIdx.x & 31;
    const int k = load_key(key, gw);
    const float4* a = (const float4*)(g_zimg + (size_t)gw * DIM);
    const float4* v = (const float4*)(g_ztxt + (size_t)k * DIM);
    float s = 0.0f;
    #pragma unroll
    for (int j = 0; j < 4; j++) {
        float4 x = a[lane + 32 * j], y = v[lane + 32 * j];
        s += x.x * y.x + x.y * y.y + x.z * y.z + x.w * y.w;
    }
    #pragma unroll
    for (int o = 16; o > 0; o >>= 1) s += __shfl_xor_sync(0xFFFFFFFFu, s, o);
    if (lane == 0) {
        float lp = s * expf(log_t_p[0]) + bias_p[0];
        float p = softplus_f(-lp);
        g_pploss[gw] = p;
        atomicMin(&g_segmin[k], __float_as_uint(p));
    }
}

// K5: first-index argmin among exact-min matches
__global__ void argmin_kernel(const int* __restrict__ key) {
    int i = blockIdx.x * blockDim.x + threadIdx.x;
    if (i >= S_IMG) return;
    int k = load_key(key, i);
    if (__float_as_uint(g_pploss[i]) == g_segmin[k])
        atomicMin(&g_sel[k], i);
}

// K6: selected indices (as float) to d_out
__global__ void sel_kernel(float* __restrict__ out_sel) {
    int n = blockIdx.x * blockDim.x + threadIdx.x;
    if (n >= N_TXT) return;
    int sv = g_sel[n];
    out_sel[n] = (float)(sv < S_IMG ? sv : -1);
}

// ---------------------------------------------------------------------------
// K7: final_logits = row gather of all_pairs (bias if invalid) + row loss sums
// ---------------------------------------------------------------------------
__global__ void __launch_bounds__(256)
final_kernel(const float* __restrict__ AP, float* __restrict__ FL,
             const float* __restrict__ bias_p) {
    const int n = blockIdx.x;
    const int sv = g_sel[n];
    const bool valid = sv < S_IMG;
    const float b = bias_p[0];
    const float* src = AP + (size_t)(valid ? sv : 0) * N_TXT;

    float sum = 0.0f;
    for (int j = threadIdx.x; j < N_TXT; j += 256) {
        float v = valid ? src[j] : b;
        FL[(size_t)n * N_TXT + j] = v;
        float lbl = (j == n) ? 1.0f : -1.0f;
        sum += softplus_f(-(lbl * v));
    }
    __shared__ float sm[256];
    sm[threadIdx.x] = sum;
    __syncthreads();
    #pragma unroll
    for (int o = 128; o > 0; o >>= 1) {
        if (threadIdx.x < o) sm[threadIdx.x] += sm[threadIdx.x + o];
        __syncthreads();
    }
    if (threadIdx.x == 0) g_rowsum[n] = sm[0];
}

// K8: final loss reduction (double)
__global__ void loss_kernel(float* __restrict__ out_loss) {
    __shared__ double sd[256];
    double s = 0.0;
    for (int n = threadIdx.x; n < N_TXT; n += 256) s += (double)g_rowsum[n];
    sd[threadIdx.x] = s;
    __syncthreads();
    #pragma unroll
    for (int o = 128; o > 0; o >>= 1) {
        if (threadIdx.x < o) sd[threadIdx.x] += sd[threadIdx.x + o];
        __syncthreads();
    }
    if (threadIdx.x == 0) out_loss[0] = (float)(sd[0] / (double)N_TXT);
}

// ---------------------------------------------------------------------------
extern "C" void kernel_launch(void* const* d_in, const int* in_sizes, int n_in,
                              void* d_out, int out_size) {
    const float* img   = (const float*)d_in[0];
    const float* txt   = (const float*)d_in[1];
    const int*   key   = (const int*)d_in[2];
    const float* log_t = (const float*)d_in[3];
    const float* bias  = (const float*)d_in[4];
    float* out = (float*)d_out;
    (void)in_sizes; (void)n_in; (void)out_size;

    float* out_sel  = out + OFF_SEL;
    float* out_zimg = out + OFF_ZIMG;
    float* out_ztxt = out + OFF_ZTXT;
    float* out_ap   = out + OFF_AP;
    float* out_fl   = out + OFF_FL;

    static int smem_cfg = 0;
    const int smem_bytes = NSTAGE * STAGE_SB;   // 36864
    if (!smem_cfg) {
        cudaFuncSetAttribute(gemm_hmma_kernel,
                             cudaFuncAttributeMaxDynamicSharedMemorySize, smem_bytes);
        smem_cfg = 1;
    }

    init_kernel<<<(N_TXT + 255) / 256, 256>>>();
    detect_key_kernel<<<(S_IMG / 2 + 255) / 256, 256>>>(key);
    norm_img_kernel<<<S_IMG, 128>>>(img, out_zimg);
    norm_txt_kernel<<<N_TXT, 128>>>(txt, out_ztxt);

    dim3 grid(N_TXT / 128, S_IMG / 128);
    gemm_hmma_kernel<<<grid, 256, smem_bytes>>>(out_ap, log_t, bias);

    tp_kernel<<<(S_IMG * 32 + 255) / 256, 256>>>(key, log_t, bias);
    argmin_kernel<<<(S_IMG + 255) / 256, 256>>>(key);
    sel_kernel<<<(N_TXT + 255) / 256, 256>>>(out_sel);

    final_kernel<<<N_TXT, 256>>>(out_ap, out_fl, bias);
    loss_kernel<<<1, 256>>>(out);
}